// round 8
// baseline (speedup 1.0000x reference)
#include <cuda_runtime.h>

#define N 2048
#define HID 128
#define HEADS 8
#define QT 64            // queries per attn block (2 per thread-lane)
#define KT 8             // keys per smem tile
#define SSPLIT 16        // KV splits
#define KS (N / SSPLIT)  // 128 keys per split
#define NT (KS / KT)     // 16 tiles
#define TILE_F (KT * HID)
#define LOG2E 1.4426950408889634f
#define SCALE 0.25f      // HEAD_DIM^-0.5

// ---------------- scratch (device globals) ----------------------------------
__device__ __align__(16) float g_q[N * HID];
__device__ __align__(16) float g_k[N * HID];
__device__ __align__(16) float g_v[N * HID];
__device__ __align__(16) float g_plh[N * HEADS * SSPLIT];        // [q][h][split]
__device__ __align__(16) float g_pacc[(size_t)N * SSPLIT * HID]; // [q][split][h*16+d]

// ---------------- packed fp32x2 + fast exp2 helpers -------------------------
union F2U { float2 f2; unsigned long long u; };

__device__ __forceinline__ float2 ffma2(float2 a, float2 b, float2 c) {
    F2U ua, ub, uc, ur;
    ua.f2 = a; ub.f2 = b; uc.f2 = c;
    asm("fma.rn.f32x2 %0, %1, %2, %3;" : "=l"(ur.u) : "l"(ua.u), "l"(ub.u), "l"(uc.u));
    return ur.f2;
}
__device__ __forceinline__ float2 fmul2(float2 a, float2 b) {
    F2U ua, ub, ur;
    ua.f2 = a; ub.f2 = b;
    asm("mul.rn.f32x2 %0, %1, %2;" : "=l"(ur.u) : "l"(ua.u), "l"(ub.u));
    return ur.f2;
}
__device__ __forceinline__ float ex2f(float x) {
    float y;
    asm("ex2.approx.f32 %0, %1;" : "=f"(y) : "f"(x));
    return y;
}
__device__ __forceinline__ float2 f2(float a, float b) { return make_float2(a, b); }

#define CP16(dst_u32, src_ptr) \
    asm volatile("cp.async.ca.shared.global [%0], [%1], 16;" :: "r"(dst_u32), "l"(src_ptr))
#define CPCOMMIT() asm volatile("cp.async.commit_group;")
#define CPWAIT1()  asm volatile("cp.async.wait_group 1;")

// ---------------- no-op spacers (keep attn as ncu's 4th launch) --------------
__global__ void spacer_kernel() {}

// ---------------- QKV projection (R2 structure — measured 13.1us) -----------
// grid (N/16, 3), 128 threads. q pre-scaled by SCALE*LOG2E.
__global__ void __launch_bounds__(128) proj_qkv_kernel(
    const float* __restrict__ x,
    const float* __restrict__ Wq, const float* __restrict__ bq,
    const float* __restrict__ Wk, const float* __restrict__ bk,
    const float* __restrict__ Wv, const float* __restrict__ bv)
{
    __shared__ float xs[16 * HID];     // 8 KB
    __shared__ float Wt[128 * 68];     // 34.8 KB, padded stride 68
    const int tid  = threadIdx.x;
    const int row0 = blockIdx.x * 16;
    const int which = blockIdx.y;
    const float* __restrict__ W = (which == 0) ? Wq : (which == 1) ? Wk : Wv;
    const float* __restrict__ b = (which == 0) ? bq : (which == 1) ? bk : bv;
    float* out = (which == 0) ? g_q : (which == 1) ? g_k : g_v;
    const float osc = (which == 0) ? (SCALE * LOG2E) : 1.0f;

    {   // stage x rows (coalesced)
        const float4* x4 = (const float4*)(x + (size_t)row0 * HID);
        #pragma unroll
        for (int i = 0; i < 4; i++)
            ((float4*)xs)[tid + 128 * i] = x4[tid + 128 * i];
    }

    float2 acc2[16];
    #pragma unroll
    for (int r = 0; r < 16; r++) acc2[r] = f2(0.f, 0.f);

    #pragma unroll
    for (int cj = 0; cj < 2; cj++) {
        __syncthreads();
        #pragma unroll
        for (int i = 0; i < 16; i++) {
            int fidx = tid + 128 * i;
            int c = fidx >> 4, jq = fidx & 15;
            *(float4*)(Wt + c * 68 + jq * 4) =
                *(const float4*)(W + (size_t)c * HID + cj * 64 + jq * 4);
        }
        __syncthreads();
        #pragma unroll
        for (int jq = 0; jq < 16; jq++) {
            float4 w = *(const float4*)(Wt + tid * 68 + jq * 4);
            float2 wxy = f2(w.x, w.y), wzw = f2(w.z, w.w);
            #pragma unroll
            for (int r = 0; r < 16; r++) {
                float4 xv = *(const float4*)(xs + r * HID + cj * 64 + jq * 4);
                acc2[r] = ffma2(wxy, f2(xv.x, xv.y), acc2[r]);
                acc2[r] = ffma2(wzw, f2(xv.z, xv.w), acc2[r]);
            }
        }
    }
    const float bb = b[tid];
    #pragma unroll
    for (int r = 0; r < 16; r++)
        out[(size_t)(row0 + r) * HID + tid] = (acc2[r].x + acc2[r].y + bb) * osc;
}

// ---------------- fused attention: 2 queries/thread -------------------------
// grid (N/QT, SSPLIT), 256 threads. warp = head, lane = queries (ql, ql+32).
// No-max softmax in log2 domain. KV: cp.async ring-3. Bias: reg prefetch 1
// tile ahead, transformed (b*LOG2E + pen) into stride-65 smem (reads CF).
// K/V broadcast LDS amortized over 2 queries -> L1 wavefronts/cell halved.
__global__ void __launch_bounds__(256, 2) attn_kernel(
    const float* __restrict__ bias, const unsigned char* __restrict__ mask)
{
    __shared__ float sKV[2][3][TILE_F];      // 24 KB
    __shared__ float sB[2][QT * 65];         // 33.3 KB
    __shared__ float sPen[KS];               // 0.5 KB

    const int tid = threadIdx.x;
    const int h   = tid >> 5;
    const int ql  = tid & 31;
    const int qb  = blockIdx.x * QT;
    const int q1  = qb + ql;
    const int q2  = q1 + 32;
    const int split = blockIdx.y;
    const int k0  = split * KS;

    if (tid < KS) sPen[tid] = mask[k0 + tid] ? -1e30f : 0.0f;

    const float* gK = g_k + (size_t)k0 * HID;
    const float* gV = g_v + (size_t)k0 * HID;
    const unsigned sKa = (unsigned)__cvta_generic_to_shared(&sKV[0][0][0]);
    const unsigned sVa = sKa + 3 * TILE_F * 4;

    // KV tiles 0,1 in flight (1024 floats per tile, 1 float4/thread)
    CP16(sKa + tid * 16, gK + tid * 4);
    CP16(sVa + tid * 16, gV + tid * 4);
    CPCOMMIT();
    CP16(sKa + TILE_F * 4 + tid * 16, gK + TILE_F + tid * 4);
    CP16(sVa + TILE_F * 4 + tid * 16, gV + TILE_F + tid * 4);
    CPCOMMIT();

    // bias prefetch: thread owns row qrow (0..63), cols kko*16..+15
    const int qrow = tid >> 2;
    const int kko  = tid & 3;
    const float* gbRow = bias + (size_t)(qb + qrow) * (N * HEADS)
                              + (size_t)k0 * HEADS + kko * 16;
    float4 bb0 = *(const float4*)(gbRow);
    float4 bb1 = *(const float4*)(gbRow + 4);
    float4 bb2 = *(const float4*)(gbRow + 8);
    float4 bb3 = *(const float4*)(gbRow + 12);

    // q vectors for both queries (packed along d)
    float2 qv1[8], qv2[8];
    {
        const float4* qp1 = (const float4*)(g_q + (size_t)q1 * HID + h * 16);
        const float4* qp2 = (const float4*)(g_q + (size_t)q2 * HID + h * 16);
        #pragma unroll
        for (int i = 0; i < 4; i++) {
            float4 a = qp1[i], c = qp2[i];
            qv1[2 * i]     = f2(a.x, a.y);  qv1[2 * i + 1] = f2(a.z, a.w);
            qv2[2 * i]     = f2(c.x, c.y);  qv2[2 * i + 1] = f2(c.z, c.w);
        }
    }

    float l1 = 0.f, l2 = 0.f;
    float2 a1[8], a2[8];
    #pragma unroll
    for (int i = 0; i < 8; i++) { a1[i] = f2(0.f, 0.f); a2[i] = f2(0.f, 0.f); }

    __syncthreads();   // sPen visible before first transform

    for (int t = 0; t < NT; t++) {
        // transform bias tile t: 16 floats = keys {2*kko, 2*kko+1}, 8 heads each
        {
            float penA = sPen[t * KT + kko * 2];
            float penB = sPen[t * KT + kko * 2 + 1];
            float* dst = &sB[t & 1][qrow * 65 + kko * 16];
            dst[0]  = fmaf(bb0.x, LOG2E, penA);
            dst[1]  = fmaf(bb0.y, LOG2E, penA);
            dst[2]  = fmaf(bb0.z, LOG2E, penA);
            dst[3]  = fmaf(bb0.w, LOG2E, penA);
            dst[4]  = fmaf(bb1.x, LOG2E, penA);
            dst[5]  = fmaf(bb1.y, LOG2E, penA);
            dst[6]  = fmaf(bb1.z, LOG2E, penA);
            dst[7]  = fmaf(bb1.w, LOG2E, penA);
            dst[8]  = fmaf(bb2.x, LOG2E, penB);
            dst[9]  = fmaf(bb2.y, LOG2E, penB);
            dst[10] = fmaf(bb2.z, LOG2E, penB);
            dst[11] = fmaf(bb2.w, LOG2E, penB);
            dst[12] = fmaf(bb3.x, LOG2E, penB);
            dst[13] = fmaf(bb3.y, LOG2E, penB);
            dst[14] = fmaf(bb3.z, LOG2E, penB);
            dst[15] = fmaf(bb3.w, LOG2E, penB);
        }
        // prefetch bias tile t+1 (KT*HEADS = 64 floats per tile per row)
        if (t + 1 < NT) {
            const float* nb = gbRow + (size_t)(t + 1) * (KT * HEADS);
            bb0 = *(const float4*)(nb);
            bb1 = *(const float4*)(nb + 4);
            bb2 = *(const float4*)(nb + 8);
            bb3 = *(const float4*)(nb + 12);
        }
        CPWAIT1();                 // KV tile t resident
        __syncthreads();           // publish sB tile + KV block-wide
        if (t + 2 < NT) {          // KV tile t+2 into ring (readers done)
            int bidx = (t + 2) % 3;
            CP16(sKa + (bidx * TILE_F + tid * 4) * 4, gK + (size_t)(t + 2) * TILE_F + tid * 4);
            CP16(sVa + (bidx * TILE_F + tid * 4) * 4, gV + (size_t)(t + 2) * TILE_F + tid * 4);
        }
        CPCOMMIT();

        const float* kbuf  = sKV[0][t % 3];
        const float* vbuf  = sKV[1][t % 3];
        const float* brow1 = &sB[t & 1][ql * 65 + h];
        const float* brow2 = brow1 + 32 * 65;
        #pragma unroll
        for (int kk = 0; kk < KT; kk++) {
            const float4* kp = (const float4*)(kbuf + kk * HID + h * 16);
            float4 u0 = kp[0], u1 = kp[1];
            float2 d0 = fmul2(qv1[0], f2(u0.x, u0.y));
            float2 e0 = fmul2(qv2[0], f2(u0.x, u0.y));
            d0 = ffma2(qv1[1], f2(u0.z, u0.w), d0);
            e0 = ffma2(qv2[1], f2(u0.z, u0.w), e0);
            d0 = ffma2(qv1[2], f2(u1.x, u1.y), d0);
            e0 = ffma2(qv2[2], f2(u1.x, u1.y), e0);
            d0 = ffma2(qv1[3], f2(u1.z, u1.w), d0);
            e0 = ffma2(qv2[3], f2(u1.z, u1.w), e0);
            float4 u2 = kp[2], u3 = kp[3];
            d0 = ffma2(qv1[4], f2(u2.x, u2.y), d0);
            e0 = ffma2(qv2[4], f2(u2.x, u2.y), e0);
            d0 = ffma2(qv1[5], f2(u2.z, u2.w), d0);
            e0 = ffma2(qv2[5], f2(u2.z, u2.w), e0);
            d0 = ffma2(qv1[6], f2(u3.x, u3.y), d0);
            e0 = ffma2(qv2[6], f2(u3.x, u3.y), e0);
            d0 = ffma2(qv1[7], f2(u3.z, u3.w), d0);
            e0 = ffma2(qv2[7], f2(u3.z, u3.w), e0);
            float s1 = (d0.x + d0.y) + brow1[kk * 8];
            float s2 = (e0.x + e0.y) + brow2[kk * 8];
            float p1 = ex2f(s1), p2 = ex2f(s2);
            l1 += p1; l2 += p2;
            float2 p11 = f2(p1, p1), p22 = f2(p2, p2);
            const float4* vp = (const float4*)(vbuf + kk * HID + h * 16);
            float4 v0 = vp[0], v1 = vp[1];
            a1[0] = ffma2(p11, f2(v0.x, v0.y), a1[0]);
            a2[0] = ffma2(p22, f2(v0.x, v0.y), a2[0]);
            a1[1] = ffma2(p11, f2(v0.z, v0.w), a1[1]);
            a2[1] = ffma2(p22, f2(v0.z, v0.w), a2[1]);
            a1[2] = ffma2(p11, f2(v1.x, v1.y), a1[2]);
            a2[2] = ffma2(p22, f2(v1.x, v1.y), a2[2]);
            a1[3] = ffma2(p11, f2(v1.z, v1.w), a1[3]);
            a2[3] = ffma2(p22, f2(v1.z, v1.w), a2[3]);
            float4 v2 = vp[2], v3 = vp[3];
            a1[4] = ffma2(p11, f2(v2.x, v2.y), a1[4]);
            a2[4] = ffma2(p22, f2(v2.x, v2.y), a2[4]);
            a1[5] = ffma2(p11, f2(v2.z, v2.w), a1[5]);
            a2[5] = ffma2(p22, f2(v2.z, v2.w), a2[5]);
            a1[6] = ffma2(p11, f2(v3.x, v3.y), a1[6]);
            a2[6] = ffma2(p22, f2(v3.x, v3.y), a2[6]);
            a1[7] = ffma2(p11, f2(v3.z, v3.w), a1[7]);
            a2[7] = ffma2(p22, f2(v3.z, v3.w), a2[7]);
        }
    }

    g_plh[(q1 * HEADS + h) * SSPLIT + split] = l1;
    g_plh[(q2 * HEADS + h) * SSPLIT + split] = l2;
    {
        const float4* s1p = (const float4*)a1;
        const float4* s2p = (const float4*)a2;
        float4* d1 = (float4*)(g_pacc + ((size_t)q1 * SSPLIT + split) * HID + h * 16);
        float4* d2 = (float4*)(g_pacc + ((size_t)q2 * SSPLIT + split) * HID + h * 16);
        #pragma unroll
        for (int i = 0; i < 4; i++) { d1[i] = s1p[i]; d2[i] = s2p[i]; }
    }
}

// ---------------- fused merge + output projection (R2 structure) ------------
__global__ void __launch_bounds__(128) oproj_kernel(
    const float* __restrict__ Wo, const float* __restrict__ bo,
    float* __restrict__ out)
{
    __shared__ __align__(16) float xs[16 * HID];
    __shared__ float Wt[128 * 68];
    const int tid  = threadIdx.x;
    const int row0 = blockIdx.x * 16;
    const int myh  = tid >> 4;

    #pragma unroll
    for (int r = 0; r < 16; r++) {
        const int q = row0 + r;
        float lsum = 0.f;
        const float4* lp = (const float4*)(g_plh + (q * HEADS + myh) * SSPLIT);
        #pragma unroll
        for (int i = 0; i < 4; i++) {
            float4 t = lp[i];
            lsum += (t.x + t.y) + (t.z + t.w);
        }
        float v = 0.f;
        const float* pa = g_pacc + (size_t)q * SSPLIT * HID + tid;
        #pragma unroll
        for (int s = 0; s < SSPLIT; s++) v += pa[s * HID];
        xs[r * HID + tid] = v / lsum;
    }

    float2 acc2[16];
    #pragma unroll
    for (int r = 0; r < 16; r++) acc2[r] = f2(0.f, 0.f);

    #pragma unroll
    for (int cj = 0; cj < 2; cj++) {
        __syncthreads();
        #pragma unroll
        for (int i = 0; i < 16; i++) {
            int fidx = tid + 128 * i;
            int c = fidx >> 4, jq = fidx & 15;
            *(float4*)(Wt + c * 68 + jq * 4) =
                *(const float4*)(Wo + (size_t)c * HID + cj * 64 + jq * 4);
        }
        __syncthreads();
        #pragma unroll
        for (int jq = 0; jq < 16; jq++) {
            float4 w = *(const float4*)(Wt + tid * 68 + jq * 4);
            float2 wxy = f2(w.x, w.y), wzw = f2(w.z, w.w);
            #pragma unroll
            for (int r = 0; r < 16; r++) {
                float4 xv = *(const float4*)(xs + r * HID + cj * 64 + jq * 4);
                acc2[r] = ffma2(wxy, f2(xv.x, xv.y), acc2[r]);
                acc2[r] = ffma2(wzw, f2(xv.z, xv.w), acc2[r]);
            }
        }
    }
    const float bb = bo[tid];
    #pragma unroll
    for (int r = 0; r < 16; r++)
        out[(size_t)(row0 + r) * HID + tid] = acc2[r].x + acc2[r].y + bb;
}

// ---------------- launcher ---------------------------------------------------
extern "C" void kernel_launch(void* const* d_in, const int* in_sizes, int n_in,
                              void* d_out, int out_size)
{
    const float* x    = (const float*)d_in[0];
    const float* bias = (const float*)d_in[1];
    const unsigned char* mask = (const unsigned char*)d_in[2];
    const float* Wq = (const float*)d_in[3];
    const float* bq = (const float*)d_in[4];
    const float* Wk = (const float*)d_in[5];
    const float* bk = (const float*)d_in[6];
    const float* Wv = (const float*)d_in[7];
    const float* bv = (const float*)d_in[8];
    const float* Wo = (const float*)d_in[9];
    const float* bo = (const float*)d_in[10];

    // spacers keep attn as the 4th launch (the one ncu captures)
    spacer_kernel<<<1, 32>>>();
    spacer_kernel<<<1, 32>>>();
    proj_qkv_kernel<<<dim3(N / 16, 3), 128>>>(x, Wq, bq, Wk, bk, Wv, bv);
    attn_kernel<<<dim3(N / QT, SSPLIT), 256>>>(bias, mask);
    oproj_kernel<<<N / 16, 128>>>(Wo, bo, (float*)d_out);
}

// round 9
// speedup vs baseline: 1.2623x; 1.2623x over previous
#include <cuda_runtime.h>

#define N 2048
#define HID 128
#define HEADS 8
#define QT 32            // queries per attn block
#define KT 8             // keys per tile
#define SSPLIT 8         // KV splits
#define KS (N / SSPLIT)  // 256 keys per split
#define NT (KS / KT)     // 32 tiles
#define LOG2E 1.4426950408889634f
#define SCALE 0.25f

// ---------------- scratch (device globals) ----------------------------------
__device__ __align__(16) float g_q[N * HID];
__device__ __align__(16) float g_k[N * HID];
__device__ __align__(16) float g_v[N * HID];
__device__ __align__(16) float g_plh[N * HEADS * SSPLIT];        // [q][h][split]
__device__ __align__(16) float g_pacc[(size_t)N * SSPLIT * HID]; // [q][split][h*16+d]

// ---------------- helpers ----------------------------------------------------
union F2U { float2 f2; unsigned long long u; };

__device__ __forceinline__ float2 ffma2(float2 a, float2 b, float2 c) {
    F2U ua, ub, uc, ur;
    ua.f2 = a; ub.f2 = b; uc.f2 = c;
    asm("fma.rn.f32x2 %0, %1, %2, %3;" : "=l"(ur.u) : "l"(ua.u), "l"(ub.u), "l"(uc.u));
    return ur.f2;
}
__device__ __forceinline__ float ex2f(float x) {
    float y;
    asm("ex2.approx.f32 %0, %1;" : "=f"(y) : "f"(x));
    return y;
}
__device__ __forceinline__ float2 f2(float a, float b) { return make_float2(a, b); }

__device__ __forceinline__ unsigned cvt_tf32(float x) {
    unsigned r;
    asm("cvt.rna.tf32.f32 %0, %1;" : "=r"(r) : "f"(x));
    return r;
}
// m16n8k8 tf32: D += A*B
__device__ __forceinline__ void mma8(float* c, const unsigned* a, const unsigned* b) {
    asm volatile(
        "mma.sync.aligned.m16n8k8.row.col.f32.tf32.tf32.f32 "
        "{%0,%1,%2,%3}, {%4,%5,%6,%7}, {%8,%9}, {%0,%1,%2,%3};"
        : "+f"(c[0]), "+f"(c[1]), "+f"(c[2]), "+f"(c[3])
        : "r"(a[0]), "r"(a[1]), "r"(a[2]), "r"(a[3]), "r"(b[0]), "r"(b[1]));
}

#define CP16(dst_u32, src_ptr) \
    asm volatile("cp.async.ca.shared.global [%0], [%1], 16;" :: "r"(dst_u32), "l"(src_ptr))
#define CPCOMMIT() asm volatile("cp.async.commit_group;")
#define CPWAIT1()  asm volatile("cp.async.wait_group 1;")

__global__ void spacer_kernel() {}

// ---------------- QKV projection (R2 structure, measured 13.1us) ------------
__global__ void __launch_bounds__(128) proj_qkv_kernel(
    const float* __restrict__ x,
    const float* __restrict__ Wq, const float* __restrict__ bq,
    const float* __restrict__ Wk, const float* __restrict__ bk,
    const float* __restrict__ Wv, const float* __restrict__ bv)
{
    __shared__ float xs[16 * HID];
    __shared__ float Wt[128 * 68];
    const int tid  = threadIdx.x;
    const int row0 = blockIdx.x * 16;
    const int which = blockIdx.y;
    const float* __restrict__ W = (which == 0) ? Wq : (which == 1) ? Wk : Wv;
    const float* __restrict__ b = (which == 0) ? bq : (which == 1) ? bk : bv;
    float* out = (which == 0) ? g_q : (which == 1) ? g_k : g_v;
    const float osc = (which == 0) ? (SCALE * LOG2E) : 1.0f;

    {
        const float4* x4 = (const float4*)(x + (size_t)row0 * HID);
        #pragma unroll
        for (int i = 0; i < 4; i++)
            ((float4*)xs)[tid + 128 * i] = x4[tid + 128 * i];
    }
    float2 acc2[16];
    #pragma unroll
    for (int r = 0; r < 16; r++) acc2[r] = f2(0.f, 0.f);

    #pragma unroll
    for (int cj = 0; cj < 2; cj++) {
        __syncthreads();
        #pragma unroll
        for (int i = 0; i < 16; i++) {
            int fidx = tid + 128 * i;
            int c = fidx >> 4, jq = fidx & 15;
            *(float4*)(Wt + c * 68 + jq * 4) =
                *(const float4*)(W + (size_t)c * HID + cj * 64 + jq * 4);
        }
        __syncthreads();
        #pragma unroll
        for (int jq = 0; jq < 16; jq++) {
            float4 w = *(const float4*)(Wt + tid * 68 + jq * 4);
            float2 wxy = f2(w.x, w.y), wzw = f2(w.z, w.w);
            #pragma unroll
            for (int r = 0; r < 16; r++) {
                float4 xv = *(const float4*)(xs + r * HID + cj * 64 + jq * 4);
                acc2[r] = ffma2(wxy, f2(xv.x, xv.y), acc2[r]);
                acc2[r] = ffma2(wzw, f2(xv.z, xv.w), acc2[r]);
            }
        }
    }
    const float bb = b[tid];
    #pragma unroll
    for (int r = 0; r < 16; r++)
        out[(size_t)(row0 + r) * HID + tid] = (acc2[r].x + acc2[r].y + bb) * osc;
}

// ---------------- fused attention on tensor pipe (tf32 3-term) --------------
// grid (N/32, SSPLIT), 256 threads, warp = head.
// S[32x8] = Q K^T via m16n8k8 (2 m-tiles x 2 k-steps x 3 terms), bias+mask
// folded in log2 domain, p = ex2(s) (no-max softmax), O += P V via m16n8k8
// (2 m x 2 n x 3 terms). P C-frag -> A-frag remap via shuffles.
// Strides: K 132 (banks 4g+tq CF), V 136 (banks 8tq+g CF), bias [h][q][k].
__global__ void __launch_bounds__(256, 2) attn_kernel(
    const float* __restrict__ bias, const unsigned char* __restrict__ mask)
{
    __shared__ float sK[3 * 8 * 132];    // 12.7 KB
    __shared__ float sV[3 * 8 * 136];    // 13.0 KB
    __shared__ float sB[2][2048];        // 16 KB  [buf][h][q][k]
    __shared__ float sPen[KS];           // 1 KB

    const int tid = threadIdx.x;
    const int h   = tid >> 5;
    const int ln  = tid & 31;
    const int g   = ln >> 2;             // groupID (0..7)
    const int tq  = ln & 3;              // thread in group
    const int qb  = blockIdx.x * QT;
    const int split = blockIdx.y;
    const int k0  = split * KS;

    sPen[tid] = mask[k0 + tid] ? -1e30f : 0.0f;   // KS == 256

    const float* gK = g_k + (size_t)k0 * HID;
    const float* gV = g_v + (size_t)k0 * HID;
    const unsigned sKa = (unsigned)__cvta_generic_to_shared(sK);
    const unsigned sVa = (unsigned)__cvta_generic_to_shared(sV);

    // prologue: KV tiles 0,1 (8 rows x 128 floats each; 1 float4/thread/tensor)
    {
        const int row = tid >> 5, c4 = tid & 31;
        CP16(sKa + (row * 132 + c4 * 4) * 4, gK + tid * 4);
        CP16(sVa + (row * 136 + c4 * 4) * 4, gV + tid * 4);
        CPCOMMIT();
        CP16(sKa + (1056 + row * 132 + c4 * 4) * 4, gK + 1024 + tid * 4);
        CP16(sVa + (1088 + row * 136 + c4 * 4) * 4, gV + 1024 + tid * 4);
        CPCOMMIT();
    }

    // bias staging ownership: thread = (q=tid>>3, key=tid&7); 8 heads per thread
    const int bq = tid >> 3;
    const int bk = tid & 7;
    const float* gb = bias + ((size_t)(qb + bq) * N + (size_t)(k0 + bk)) * HEADS;
    float4 bb0 = *(const float4*)(gb);
    float4 bb1 = *(const float4*)(gb + 4);

    // Q fragments (loop-invariant), hi/lo tf32 split.
    // A-frag m16n8k8: a0=(g,tq) a1=(g+8,tq) a2=(g,tq+4) a3=(g+8,tq+4)
    unsigned Qh[2][2][4], Ql[2][2][4];
    #pragma unroll
    for (int m = 0; m < 2; m++) {
        #pragma unroll
        for (int ks = 0; ks < 2; ks++) {
            const int q0 = qb + m * 16 + g;
            const int d0 = h * 16 + ks * 8 + tq;
            float v0 = g_q[(size_t)q0 * HID + d0];
            float v1 = g_q[(size_t)(q0 + 8) * HID + d0];
            float v2 = g_q[(size_t)q0 * HID + d0 + 4];
            float v3 = g_q[(size_t)(q0 + 8) * HID + d0 + 4];
            unsigned u0 = cvt_tf32(v0), u1 = cvt_tf32(v1);
            unsigned u2 = cvt_tf32(v2), u3 = cvt_tf32(v3);
            Qh[m][ks][0] = u0; Qh[m][ks][1] = u1; Qh[m][ks][2] = u2; Qh[m][ks][3] = u3;
            Ql[m][ks][0] = cvt_tf32(v0 - __uint_as_float(u0));
            Ql[m][ks][1] = cvt_tf32(v1 - __uint_as_float(u1));
            Ql[m][ks][2] = cvt_tf32(v2 - __uint_as_float(u2));
            Ql[m][ks][3] = cvt_tf32(v3 - __uint_as_float(u3));
        }
    }

    float O[2][2][4];
    #pragma unroll
    for (int m = 0; m < 2; m++)
        #pragma unroll
        for (int n = 0; n < 2; n++)
            #pragma unroll
            for (int r = 0; r < 4; r++) O[m][n][r] = 0.f;
    float lacc[4] = {0.f, 0.f, 0.f, 0.f};

    __syncthreads();   // sPen visible

    for (int t = 0; t < NT; t++) {
        // stage bias tile t: sB[buf][h'][bq][bk] = bias*LOG2E + pen
        {
            float penv = sPen[t * KT + bk];
            float* d = &sB[t & 1][bq * 8 + bk];
            d[0]    = fmaf(bb0.x, LOG2E, penv);
            d[256]  = fmaf(bb0.y, LOG2E, penv);
            d[512]  = fmaf(bb0.z, LOG2E, penv);
            d[768]  = fmaf(bb0.w, LOG2E, penv);
            d[1024] = fmaf(bb1.x, LOG2E, penv);
            d[1280] = fmaf(bb1.y, LOG2E, penv);
            d[1536] = fmaf(bb1.z, LOG2E, penv);
            d[1792] = fmaf(bb1.w, LOG2E, penv);
        }
        if (t + 1 < NT) {   // prefetch bias t+1 (stride 8 keys * 8 heads)
            const float* nb = gb + (size_t)(t + 1) * 64;
            bb0 = *(const float4*)(nb);
            bb1 = *(const float4*)(nb + 4);
        }
        CPWAIT1();                 // KV tile t resident
        __syncthreads();           // publish bias t + KV t
        if (t + 2 < NT) {          // KV tile t+2 into ring (readers done)
            const int row = tid >> 5, c4 = tid & 31;
            const int s3 = (t + 2) % 3;
            CP16(sKa + (s3 * 1056 + row * 132 + c4 * 4) * 4,
                 gK + (size_t)(t + 2) * 1024 + tid * 4);
            CP16(sVa + (s3 * 1088 + row * 136 + c4 * 4) * 4,
                 gV + (size_t)(t + 2) * 1024 + tid * 4);
        }
        CPCOMMIT();

        const float* kb = sK + (t % 3) * 1056;
        const float* vb = sV + (t % 3) * 1088;
        const float* bh = &sB[t & 1][h * 256];

        // ---- K B-frags: b0=K[key=g][d=tq], b1=K[key=g][d=tq+4] (per ks) ----
        unsigned KBh[2][2], KBl[2][2];
        #pragma unroll
        for (int ks = 0; ks < 2; ks++) {
            float f0 = kb[g * 132 + h * 16 + ks * 8 + tq];
            float f1 = kb[g * 132 + h * 16 + ks * 8 + tq + 4];
            unsigned u0 = cvt_tf32(f0), u1 = cvt_tf32(f1);
            KBh[ks][0] = u0; KBh[ks][1] = u1;
            KBl[ks][0] = __float_as_uint(f0 - __uint_as_float(u0));
            KBl[ks][1] = __float_as_uint(f1 - __uint_as_float(u1));
        }
        // ---- S = Q K^T (3-term) ----
        float S[2][4];
        #pragma unroll
        for (int m = 0; m < 2; m++) {
            S[m][0] = S[m][1] = S[m][2] = S[m][3] = 0.f;
            #pragma unroll
            for (int ks = 0; ks < 2; ks++) {
                mma8(S[m], Qh[m][ks], KBh[ks]);
                mma8(S[m], Ql[m][ks], KBh[ks]);
                mma8(S[m], Qh[m][ks], KBl[ks]);
            }
        }
        // ---- bias + exp; accumulate l ----
        float P[2][4];
        #pragma unroll
        for (int m = 0; m < 2; m++) {
            float2 bA = *(const float2*)(bh + (m * 16 + g) * 8 + 2 * tq);
            float2 bB = *(const float2*)(bh + (m * 16 + g + 8) * 8 + 2 * tq);
            P[m][0] = ex2f(S[m][0] + bA.x);
            P[m][1] = ex2f(S[m][1] + bA.y);
            P[m][2] = ex2f(S[m][2] + bB.x);
            P[m][3] = ex2f(S[m][3] + bB.y);
            lacc[m * 2 + 0] += P[m][0] + P[m][1];
            lacc[m * 2 + 1] += P[m][2] + P[m][3];
        }
        // ---- V B-frags: b0=V[key=tq][d], b1=V[key=tq+4][d] (per nt) ----
        unsigned VBh[2][2], VBl[2][2];
        #pragma unroll
        for (int nt = 0; nt < 2; nt++) {
            float f0 = vb[tq * 136 + h * 16 + nt * 8 + g];
            float f1 = vb[(tq + 4) * 136 + h * 16 + nt * 8 + g];
            unsigned u0 = cvt_tf32(f0), u1 = cvt_tf32(f1);
            VBh[nt][0] = u0; VBh[nt][1] = u1;
            VBl[nt][0] = __float_as_uint(f0 - __uint_as_float(u0));
            VBl[nt][1] = __float_as_uint(f1 - __uint_as_float(u1));
        }
        // ---- P: C-frag layout -> A-frag layout via shuffles ----
        const int s0 = (ln & ~3) | (tq >> 1);
        const int s1 = s0 + 2;
        const bool odd = tq & 1;
        unsigned PAh[2][4], PAl[2][4];
        #pragma unroll
        for (int m = 0; m < 2; m++) {
            float x0, x1, a0, a1, a2, a3;
            x0 = __shfl_sync(0xffffffffu, P[m][0], s0);
            x1 = __shfl_sync(0xffffffffu, P[m][1], s0);
            a0 = odd ? x1 : x0;
            x0 = __shfl_sync(0xffffffffu, P[m][2], s0);
            x1 = __shfl_sync(0xffffffffu, P[m][3], s0);
            a1 = odd ? x1 : x0;
            x0 = __shfl_sync(0xffffffffu, P[m][0], s1);
            x1 = __shfl_sync(0xffffffffu, P[m][1], s1);
            a2 = odd ? x1 : x0;
            x0 = __shfl_sync(0xffffffffu, P[m][2], s1);
            x1 = __shfl_sync(0xffffffffu, P[m][3], s1);
            a3 = odd ? x1 : x0;
            unsigned u0 = cvt_tf32(a0), u1 = cvt_tf32(a1);
            unsigned u2 = cvt_tf32(a2), u3 = cvt_tf32(a3);
            PAh[m][0] = u0; PAh[m][1] = u1; PAh[m][2] = u2; PAh[m][3] = u3;
            PAl[m][0] = __float_as_uint(a0 - __uint_as_float(u0));
            PAl[m][1] = __float_as_uint(a1 - __uint_as_float(u1));
            PAl[m][2] = __float_as_uint(a2 - __uint_as_float(u2));
            PAl[m][3] = __float_as_uint(a3 - __uint_as_float(u3));
        }
        // ---- O += P V (3-term) ----
        #pragma unroll
        for (int m = 0; m < 2; m++) {
            #pragma unroll
            for (int nt = 0; nt < 2; nt++) {
                mma8(O[m][nt], PAh[m], VBh[nt]);
                mma8(O[m][nt], PAl[m], VBh[nt]);
                mma8(O[m][nt], PAh[m], VBl[nt]);
            }
        }
    }

    // ---- l: reduce across the 4-lane group (cols 0..7) ----
    #pragma unroll
    for (int i = 0; i < 4; i++) {
        lacc[i] += __shfl_xor_sync(0xffffffffu, lacc[i], 1);
        lacc[i] += __shfl_xor_sync(0xffffffffu, lacc[i], 2);
    }
    if (tq == 0) {
        g_plh[((qb + g) * HEADS + h) * SSPLIT + split]      = lacc[0];
        g_plh[((qb + g + 8) * HEADS + h) * SSPLIT + split]  = lacc[1];
        g_plh[((qb + g + 16) * HEADS + h) * SSPLIT + split] = lacc[2];
        g_plh[((qb + g + 24) * HEADS + h) * SSPLIT + split] = lacc[3];
    }
    // ---- O stores: rows (qb+m*16+g, +8), cols h*16+nt*8+2tq ----
    #pragma unroll
    for (int m = 0; m < 2; m++) {
        #pragma unroll
        for (int nt = 0; nt < 2; nt++) {
            const int r0 = qb + m * 16 + g;
            const int c  = h * 16 + nt * 8 + 2 * tq;
            *(float2*)(g_pacc + ((size_t)r0 * SSPLIT + split) * HID + c) =
                f2(O[m][nt][0], O[m][nt][1]);
            *(float2*)(g_pacc + ((size_t)(r0 + 8) * SSPLIT + split) * HID + c) =
                f2(O[m][nt][2], O[m][nt][3]);
        }
    }
}

// ---------------- fused merge + output projection ---------------------------
__global__ void __launch_bounds__(128) oproj_kernel(
    const float* __restrict__ Wo, const float* __restrict__ bo,
    float* __restrict__ out)
{
    __shared__ __align__(16) float xs[16 * HID];
    __shared__ float Wt[128 * 68];
    const int tid  = threadIdx.x;
    const int row0 = blockIdx.x * 16;
    const int myh  = tid >> 4;

    #pragma unroll
    for (int r = 0; r < 16; r++) {
        const int q = row0 + r;
        float lsum;
        {
            const float4* lp = (const float4*)(g_plh + (q * HEADS + myh) * SSPLIT);
            float4 t0 = lp[0], t1 = lp[1];
            lsum = ((t0.x + t0.y) + (t0.z + t0.w))
                 + ((t1.x + t1.y) + (t1.z + t1.w));
        }
        float v = 0.f;
        const float* pa = g_pacc + (size_t)q * SSPLIT * HID + tid;
        #pragma unroll
        for (int s = 0; s < SSPLIT; s++) v += pa[s * HID];
        xs[r * HID + tid] = v / lsum;
    }

    float2 acc2[16];
    #pragma unroll
    for (int r = 0; r < 16; r++) acc2[r] = f2(0.f, 0.f);

    #pragma unroll
    for (int cj = 0; cj < 2; cj++) {
        __syncthreads();
        #pragma unroll
        for (int i = 0; i < 16; i++) {
            int fidx = tid + 128 * i;
            int c = fidx >> 4, jq = fidx & 15;
            *(float4*)(Wt + c * 68 + jq * 4) =
                *(const float4*)(Wo + (size_t)c * HID + cj * 64 + jq * 4);
        }
        __syncthreads();
        #pragma unroll
        for (int jq = 0; jq < 16; jq++) {
            float4 w = *(const float4*)(Wt + tid * 68 + jq * 4);
            float2 wxy = f2(w.x, w.y), wzw = f2(w.z, w.w);
            #pragma unroll
            for (int r = 0; r < 16; r++) {
                float4 xv = *(const float4*)(xs + r * HID + cj * 64 + jq * 4);
                acc2[r] = ffma2(wxy, f2(xv.x, xv.y), acc2[r]);
                acc2[r] = ffma2(wzw, f2(xv.z, xv.w), acc2[r]);
            }
        }
    }
    const float bb = bo[tid];
    #pragma unroll
    for (int r = 0; r < 16; r++)
        out[(size_t)(row0 + r) * HID + tid] = acc2[r].x + acc2[r].y + bb;
}

// ---------------- launcher ---------------------------------------------------
extern "C" void kernel_launch(void* const* d_in, const int* in_sizes, int n_in,
                              void* d_out, int out_size)
{
    const float* x    = (const float*)d_in[0];
    const float* bias = (const float*)d_in[1];
    const unsigned char* mask = (const unsigned char*)d_in[2];
    const float* Wq = (const float*)d_in[3];
    const float* bq = (const float*)d_in[4];
    const float* Wk = (const float*)d_in[5];
    const float* bk = (const float*)d_in[6];
    const float* Wv = (const float*)d_in[7];
    const float* bv = (const float*)d_in[8];
    const float* Wo = (const float*)d_in[9];
    const float* bo = (const float*)d_in[10];

    // spacers keep attn as the 4th launch (the one ncu captures)
    spacer_kernel<<<1, 32>>>();
    spacer_kernel<<<1, 32>>>();
    proj_qkv_kernel<<<dim3(N / 16, 3), 128>>>(x, Wq, bq, Wk, bk, Wv, bv);
    attn_kernel<<<dim3(N / QT, SSPLIT), 256>>>(bias, mask);
    oproj_kernel<<<N / 16, 128>>>(Wo, bo, (float*)d_out);
}

// round 10
// speedup vs baseline: 1.3094x; 1.0373x over previous
#include <cuda_runtime.h>

#define N 2048
#define HID 128
#define HEADS 8
#define QT 32            // queries per attn block
#define KT 8             // keys per tile
#define SSPLIT 8         // KV splits
#define KS (N / SSPLIT)  // 256 keys per split
#define NT (KS / KT)     // 32 tiles
#define LOG2E 1.4426950408889634f
#define SCALE 0.25f

// ---------------- scratch (device globals) ----------------------------------
__device__ __align__(16) float g_q[N * HID];
__device__ __align__(16) float g_kh[N * HID];    // K tf32 hi
__device__ __align__(16) float g_kl[N * HID];    // K tf32 lo (residual)
__device__ __align__(16) float g_vh[N * HID];    // V tf32 hi
__device__ __align__(16) float g_plh[N * HEADS * SSPLIT];        // [q][h][split]
__device__ __align__(16) float g_pacc[(size_t)N * SSPLIT * HID]; // [q][split][h*16+d]

// ---------------- helpers ----------------------------------------------------
union F2U { float2 f2; unsigned long long u; };

__device__ __forceinline__ float2 ffma2(float2 a, float2 b, float2 c) {
    F2U ua, ub, uc, ur;
    ua.f2 = a; ub.f2 = b; uc.f2 = c;
    asm("fma.rn.f32x2 %0, %1, %2, %3;" : "=l"(ur.u) : "l"(ua.u), "l"(ub.u), "l"(uc.u));
    return ur.f2;
}
__device__ __forceinline__ float ex2f(float x) {
    float y;
    asm("ex2.approx.f32 %0, %1;" : "=f"(y) : "f"(x));
    return y;
}
__device__ __forceinline__ float2 f2(float a, float b) { return make_float2(a, b); }

__device__ __forceinline__ unsigned cvt_tf32(float x) {
    unsigned r;
    asm("cvt.rna.tf32.f32 %0, %1;" : "=r"(r) : "f"(x));
    return r;
}
// m16n8k8 tf32: D += A*B
__device__ __forceinline__ void mma8(float* c, const unsigned* a, const unsigned* b) {
    asm volatile(
        "mma.sync.aligned.m16n8k8.row.col.f32.tf32.tf32.f32 "
        "{%0,%1,%2,%3}, {%4,%5,%6,%7}, {%8,%9}, {%0,%1,%2,%3};"
        : "+f"(c[0]), "+f"(c[1]), "+f"(c[2]), "+f"(c[3])
        : "r"(a[0]), "r"(a[1]), "r"(a[2]), "r"(a[3]), "r"(b[0]), "r"(b[1]));
}

#define CP16(dst_u32, src_ptr) \
    asm volatile("cp.async.ca.shared.global [%0], [%1], 16;" :: "r"(dst_u32), "l"(src_ptr))
#define CPCOMMIT() asm volatile("cp.async.commit_group;")
#define CPWAIT0()  asm volatile("cp.async.wait_group 0;")

__global__ void spacer_kernel() {}

// ---------------- QKV projection (R2 structure) ------------------------------
// q pre-scaled by SCALE*LOG2E; K written as tf32 hi/lo pair; V as tf32 hi.
__global__ void __launch_bounds__(128) proj_qkv_kernel(
    const float* __restrict__ x,
    const float* __restrict__ Wq, const float* __restrict__ bq,
    const float* __restrict__ Wk, const float* __restrict__ bk,
    const float* __restrict__ Wv, const float* __restrict__ bv)
{
    __shared__ float xs[16 * HID];
    __shared__ float Wt[128 * 68];
    const int tid  = threadIdx.x;
    const int row0 = blockIdx.x * 16;
    const int which = blockIdx.y;
    const float* __restrict__ W = (which == 0) ? Wq : (which == 1) ? Wk : Wv;
    const float* __restrict__ b = (which == 0) ? bq : (which == 1) ? bk : bv;
    const float osc = (which == 0) ? (SCALE * LOG2E) : 1.0f;

    {
        const float4* x4 = (const float4*)(x + (size_t)row0 * HID);
        #pragma unroll
        for (int i = 0; i < 4; i++)
            ((float4*)xs)[tid + 128 * i] = x4[tid + 128 * i];
    }
    float2 acc2[16];
    #pragma unroll
    for (int r = 0; r < 16; r++) acc2[r] = f2(0.f, 0.f);

    #pragma unroll
    for (int cj = 0; cj < 2; cj++) {
        __syncthreads();
        #pragma unroll
        for (int i = 0; i < 16; i++) {
            int fidx = tid + 128 * i;
            int c = fidx >> 4, jq = fidx & 15;
            *(float4*)(Wt + c * 68 + jq * 4) =
                *(const float4*)(W + (size_t)c * HID + cj * 64 + jq * 4);
        }
        __syncthreads();
        #pragma unroll
        for (int jq = 0; jq < 16; jq++) {
            float4 w = *(const float4*)(Wt + tid * 68 + jq * 4);
            float2 wxy = f2(w.x, w.y), wzw = f2(w.z, w.w);
            #pragma unroll
            for (int r = 0; r < 16; r++) {
                float4 xv = *(const float4*)(xs + r * HID + cj * 64 + jq * 4);
                acc2[r] = ffma2(wxy, f2(xv.x, xv.y), acc2[r]);
                acc2[r] = ffma2(wzw, f2(xv.z, xv.w), acc2[r]);
            }
        }
    }
    const float bb = b[tid];
    #pragma unroll
    for (int r = 0; r < 16; r++) {
        const size_t idx = (size_t)(row0 + r) * HID + tid;
        float val = (acc2[r].x + acc2[r].y + bb) * osc;
        if (which == 0) {
            g_q[idx] = val;
        } else if (which == 1) {
            unsigned uh = cvt_tf32(val);
            g_kh[idx] = __uint_as_float(uh);
            g_kl[idx] = __uint_as_float(cvt_tf32(val - __uint_as_float(uh)));
        } else {
            g_vh[idx] = __uint_as_float(cvt_tf32(val));
        }
    }
}

// ---------------- fused attention on tensor pipe ----------------------------
// grid (N/32, SSPLIT), 256 threads, warp = head.
// S = QK^T 3-term tf32 (QhKh + QlKh + QhKl), K hi/lo precomputed in proj.
// p = ex2(s + bias*LOG2E + pen) (no-max softmax, log2 domain).
// O += P V 2-term (PhVh + PlVh); V pre-rounded to tf32 in proj.
// KV: cp.async ring-2, issue-after-barrier, wait_group 0. Bias: reg prefetch
// one tile ahead -> smem double buffer. One __syncthreads per tile.
__global__ void __launch_bounds__(256, 2) attn_kernel(
    const float* __restrict__ bias, const unsigned char* __restrict__ mask)
{
    __shared__ float sKh[2][8 * 132];    // 8.4 KB
    __shared__ float sKl[2][8 * 132];    // 8.4 KB
    __shared__ float sVh[2][8 * 136];    // 8.7 KB
    __shared__ float sB[2][2048];        // 16 KB  [buf][h][q][k]
    __shared__ float sPen[KS];           // 1 KB

    const int tid = threadIdx.x;
    const int h   = tid >> 5;
    const int ln  = tid & 31;
    const int g   = ln >> 2;
    const int tq  = ln & 3;
    const int qb  = blockIdx.x * QT;
    const int split = blockIdx.y;
    const int k0  = split * KS;

    sPen[tid] = mask[k0 + tid] ? -1e30f : 0.0f;   // KS == 256

    const float* gKh = g_kh + (size_t)k0 * HID;
    const float* gKl = g_kl + (size_t)k0 * HID;
    const float* gVh = g_vh + (size_t)k0 * HID;
    const unsigned aKh = (unsigned)__cvta_generic_to_shared(&sKh[0][0]);
    const unsigned aKl = (unsigned)__cvta_generic_to_shared(&sKl[0][0]);
    const unsigned aVh = (unsigned)__cvta_generic_to_shared(&sVh[0][0]);
    const int row = tid >> 5, c4 = tid & 31;

    // prologue: tile 0 into slot 0
    CP16(aKh + (row * 132 + c4 * 4) * 4, gKh + tid * 4);
    CP16(aKl + (row * 132 + c4 * 4) * 4, gKl + tid * 4);
    CP16(aVh + (row * 136 + c4 * 4) * 4, gVh + tid * 4);
    CPCOMMIT();

    // bias staging ownership: thread = (q=tid>>3, key=tid&7); 8 heads/thread
    const int bq = tid >> 3;
    const int bk = tid & 7;
    const float* gb = bias + ((size_t)(qb + bq) * N + (size_t)(k0 + bk)) * HEADS;
    float4 bb0 = *(const float4*)(gb);
    float4 bb1 = *(const float4*)(gb + 4);

    // Q fragments (loop-invariant), hi/lo tf32 split
    unsigned Qh[2][2][4], Ql[2][2][4];
    #pragma unroll
    for (int m = 0; m < 2; m++) {
        #pragma unroll
        for (int ks = 0; ks < 2; ks++) {
            const int q0 = qb + m * 16 + g;
            const int d0 = h * 16 + ks * 8 + tq;
            float v0 = g_q[(size_t)q0 * HID + d0];
            float v1 = g_q[(size_t)(q0 + 8) * HID + d0];
            float v2 = g_q[(size_t)q0 * HID + d0 + 4];
            float v3 = g_q[(size_t)(q0 + 8) * HID + d0 + 4];
            unsigned u0 = cvt_tf32(v0), u1 = cvt_tf32(v1);
            unsigned u2 = cvt_tf32(v2), u3 = cvt_tf32(v3);
            Qh[m][ks][0] = u0; Qh[m][ks][1] = u1; Qh[m][ks][2] = u2; Qh[m][ks][3] = u3;
            Ql[m][ks][0] = cvt_tf32(v0 - __uint_as_float(u0));
            Ql[m][ks][1] = cvt_tf32(v1 - __uint_as_float(u1));
            Ql[m][ks][2] = cvt_tf32(v2 - __uint_as_float(u2));
            Ql[m][ks][3] = cvt_tf32(v3 - __uint_as_float(u3));
        }
    }

    float O[2][2][4];
    #pragma unroll
    for (int m = 0; m < 2; m++)
        #pragma unroll
        for (int n = 0; n < 2; n++)
            #pragma unroll
            for (int r = 0; r < 4; r++) O[m][n][r] = 0.f;
    float lacc[4] = {0.f, 0.f, 0.f, 0.f};

    __syncthreads();   // sPen visible

    for (int t = 0; t < NT; t++) {
        // stage bias tile t into sB[t&1] (readers of this buffer = tile t-2, done)
        {
            float penv = sPen[t * KT + bk];
            float* d = &sB[t & 1][bq * 8 + bk];
            d[0]    = fmaf(bb0.x, LOG2E, penv);
            d[256]  = fmaf(bb0.y, LOG2E, penv);
            d[512]  = fmaf(bb0.z, LOG2E, penv);
            d[768]  = fmaf(bb0.w, LOG2E, penv);
            d[1024] = fmaf(bb1.x, LOG2E, penv);
            d[1280] = fmaf(bb1.y, LOG2E, penv);
            d[1536] = fmaf(bb1.z, LOG2E, penv);
            d[1792] = fmaf(bb1.w, LOG2E, penv);
        }
        if (t + 1 < NT) {   // prefetch bias t+1
            const float* nb = gb + (size_t)(t + 1) * 64;
            bb0 = *(const float4*)(nb);
            bb1 = *(const float4*)(nb + 4);
        }
        CPWAIT0();                 // KV tile t resident (this thread's copies)
        __syncthreads();           // all copies + sB(t) visible; compute(t-1) done
        if (t + 1 < NT) {          // KV t+1 into slot (t+1)&1 (readers done pre-bar)
            const int s2 = (t + 1) & 1;
            CP16(aKh + (s2 * 1056 + row * 132 + c4 * 4) * 4,
                 gKh + (size_t)(t + 1) * 1024 + tid * 4);
            CP16(aKl + (s2 * 1056 + row * 132 + c4 * 4) * 4,
                 gKl + (size_t)(t + 1) * 1024 + tid * 4);
            CP16(aVh + (s2 * 1088 + row * 136 + c4 * 4) * 4,
                 gVh + (size_t)(t + 1) * 1024 + tid * 4);
        }
        CPCOMMIT();

        const float* kh = sKh[t & 1];
        const float* kl = sKl[t & 1];
        const float* vh = sVh[t & 1];
        const float* bh = &sB[t & 1][h * 256];

        // K B-frags (raw tf32 bits from smem, no conversion)
        unsigned KBh[2][2], KBl[2][2];
        #pragma unroll
        for (int ks = 0; ks < 2; ks++) {
            const int c = h * 16 + ks * 8 + tq;
            KBh[ks][0] = __float_as_uint(kh[g * 132 + c]);
            KBh[ks][1] = __float_as_uint(kh[g * 132 + c + 4]);
            KBl[ks][0] = __float_as_uint(kl[g * 132 + c]);
            KBl[ks][1] = __float_as_uint(kl[g * 132 + c + 4]);
        }
        // S = Q K^T (3-term)
        float S[2][4];
        #pragma unroll
        for (int m = 0; m < 2; m++) {
            S[m][0] = S[m][1] = S[m][2] = S[m][3] = 0.f;
            #pragma unroll
            for (int ks = 0; ks < 2; ks++) {
                mma8(S[m], Qh[m][ks], KBh[ks]);
                mma8(S[m], Ql[m][ks], KBh[ks]);
                mma8(S[m], Qh[m][ks], KBl[ks]);
            }
        }
        // bias + exp; accumulate l
        float P[2][4];
        #pragma unroll
        for (int m = 0; m < 2; m++) {
            float2 bA = *(const float2*)(bh + (m * 16 + g) * 8 + 2 * tq);
            float2 bB = *(const float2*)(bh + (m * 16 + g + 8) * 8 + 2 * tq);
            P[m][0] = ex2f(S[m][0] + bA.x);
            P[m][1] = ex2f(S[m][1] + bA.y);
            P[m][2] = ex2f(S[m][2] + bB.x);
            P[m][3] = ex2f(S[m][3] + bB.y);
            lacc[m * 2 + 0] += P[m][0] + P[m][1];
            lacc[m * 2 + 1] += P[m][2] + P[m][3];
        }
        // V B-frags (hi only)
        unsigned VBh[2][2];
        #pragma unroll
        for (int nt = 0; nt < 2; nt++) {
            const int c = h * 16 + nt * 8 + g;
            VBh[nt][0] = __float_as_uint(vh[tq * 136 + c]);
            VBh[nt][1] = __float_as_uint(vh[(tq + 4) * 136 + c]);
        }
        // P: C-frag -> A-frag via shuffles, hi/lo split
        const int s0 = (ln & ~3) | (tq >> 1);
        const int s1 = s0 + 2;
        const bool odd = tq & 1;
        unsigned PAh[2][4], PAl[2][4];
        #pragma unroll
        for (int m = 0; m < 2; m++) {
            float x0, x1, a0, a1, a2, a3;
            x0 = __shfl_sync(0xffffffffu, P[m][0], s0);
            x1 = __shfl_sync(0xffffffffu, P[m][1], s0);
            a0 = odd ? x1 : x0;
            x0 = __shfl_sync(0xffffffffu, P[m][2], s0);
            x1 = __shfl_sync(0xffffffffu, P[m][3], s0);
            a1 = odd ? x1 : x0;
            x0 = __shfl_sync(0xffffffffu, P[m][0], s1);
            x1 = __shfl_sync(0xffffffffu, P[m][1], s1);
            a2 = odd ? x1 : x0;
            x0 = __shfl_sync(0xffffffffu, P[m][2], s1);
            x1 = __shfl_sync(0xffffffffu, P[m][3], s1);
            a3 = odd ? x1 : x0;
            unsigned u0 = cvt_tf32(a0), u1 = cvt_tf32(a1);
            unsigned u2 = cvt_tf32(a2), u3 = cvt_tf32(a3);
            PAh[m][0] = u0; PAh[m][1] = u1; PAh[m][2] = u2; PAh[m][3] = u3;
            PAl[m][0] = __float_as_uint(a0 - __uint_as_float(u0));
            PAl[m][1] = __float_as_uint(a1 - __uint_as_float(u1));
            PAl[m][2] = __float_as_uint(a2 - __uint_as_float(u2));
            PAl[m][3] = __float_as_uint(a3 - __uint_as_float(u3));
        }
        // O += P V (2-term)
        #pragma unroll
        for (int m = 0; m < 2; m++) {
            #pragma unroll
            for (int nt = 0; nt < 2; nt++) {
                mma8(O[m][nt], PAh[m], VBh[nt]);
                mma8(O[m][nt], PAl[m], VBh[nt]);
            }
        }
    }

    // l: reduce across 4-lane group
    #pragma unroll
    for (int i = 0; i < 4; i++) {
        lacc[i] += __shfl_xor_sync(0xffffffffu, lacc[i], 1);
        lacc[i] += __shfl_xor_sync(0xffffffffu, lacc[i], 2);
    }
    if (tq == 0) {
        g_plh[((qb + g) * HEADS + h) * SSPLIT + split]      = lacc[0];
        g_plh[((qb + g + 8) * HEADS + h) * SSPLIT + split]  = lacc[1];
        g_plh[((qb + g + 16) * HEADS + h) * SSPLIT + split] = lacc[2];
        g_plh[((qb + g + 24) * HEADS + h) * SSPLIT + split] = lacc[3];
    }
    #pragma unroll
    for (int m = 0; m < 2; m++) {
        #pragma unroll
        for (int nt = 0; nt < 2; nt++) {
            const int r0 = qb + m * 16 + g;
            const int c  = h * 16 + nt * 8 + 2 * tq;
            *(float2*)(g_pacc + ((size_t)r0 * SSPLIT + split) * HID + c) =
                f2(O[m][nt][0], O[m][nt][1]);
            *(float2*)(g_pacc + ((size_t)(r0 + 8) * SSPLIT + split) * HID + c) =
                f2(O[m][nt][2], O[m][nt][3]);
        }
    }
}

// ---------------- fused merge + output projection ---------------------------
__global__ void __launch_bounds__(128) oproj_kernel(
    const float* __restrict__ Wo, const float* __restrict__ bo,
    float* __restrict__ out)
{
    __shared__ __align__(16) float xs[16 * HID];
    __shared__ float Wt[128 * 68];
    const int tid  = threadIdx.x;
    const int row0 = blockIdx.x * 16;
    const int myh  = tid >> 4;

    #pragma unroll
    for (int r = 0; r < 16; r++) {
        const int q = row0 + r;
        float lsum;
        {
            const float4* lp = (const float4*)(g_plh + (q * HEADS + myh) * SSPLIT);
            float4 t0 = lp[0], t1 = lp[1];
            lsum = ((t0.x + t0.y) + (t0.z + t0.w))
                 + ((t1.x + t1.y) + (t1.z + t1.w));
        }
        float v = 0.f;
        const float* pa = g_pacc + (size_t)q * SSPLIT * HID + tid;
        #pragma unroll
        for (int s = 0; s < SSPLIT; s++) v += pa[s * HID];
        xs[r * HID + tid] = v / lsum;
    }

    float2 acc2[16];
    #pragma unroll
    for (int r = 0; r < 16; r++) acc2[r] = f2(0.f, 0.f);

    #pragma unroll
    for (int cj = 0; cj < 2; cj++) {
        __syncthreads();
        #pragma unroll
        for (int i = 0; i < 16; i++) {
            int fidx = tid + 128 * i;
            int c = fidx >> 4, jq = fidx & 15;
            *(float4*)(Wt + c * 68 + jq * 4) =
                *(const float4*)(Wo + (size_t)c * HID + cj * 64 + jq * 4);
        }
        __syncthreads();
        #pragma unroll
        for (int jq = 0; jq < 16; jq++) {
            float4 w = *(const float4*)(Wt + tid * 68 + jq * 4);
            float2 wxy = f2(w.x, w.y), wzw = f2(w.z, w.w);
            #pragma unroll
            for (int r = 0; r < 16; r++) {
                float4 xv = *(const float4*)(xs + r * HID + cj * 64 + jq * 4);
                acc2[r] = ffma2(wxy, f2(xv.x, xv.y), acc2[r]);
                acc2[r] = ffma2(wzw, f2(xv.z, xv.w), acc2[r]);
            }
        }
    }
    const float bb = bo[tid];
    #pragma unroll
    for (int r = 0; r < 16; r++)
        out[(size_t)(row0 + r) * HID + tid] = acc2[r].x + acc2[r].y + bb;
}

// ---------------- launcher ---------------------------------------------------
extern "C" void kernel_launch(void* const* d_in, const int* in_sizes, int n_in,
                              void* d_out, int out_size)
{
    const float* x    = (const float*)d_in[0];
    const float* bias = (const float*)d_in[1];
    const unsigned char* mask = (const unsigned char*)d_in[2];
    const float* Wq = (const float*)d_in[3];
    const float* bq = (const float*)d_in[4];
    const float* Wk = (const float*)d_in[5];
    const float* bk = (const float*)d_in[6];
    const float* Wv = (const float*)d_in[7];
    const float* bv = (const float*)d_in[8];
    const float* Wo = (const float*)d_in[9];
    const float* bo = (const float*)d_in[10];

    // spacers keep attn as the 4th launch (the one ncu captures)
    spacer_kernel<<<1, 32>>>();
    spacer_kernel<<<1, 32>>>();
    proj_qkv_kernel<<<dim3(N / 16, 3), 128>>>(x, Wq, bq, Wk, bk, Wv, bv);
    attn_kernel<<<dim3(N / QT, SSPLIT), 256>>>(bias, mask);
    oproj_kernel<<<N / 16, 128>>>(Wo, bo, (float*)d_out);
}